// round 16
// baseline (speedup 1.0000x reference)
#include <cuda_runtime.h>
#include <cuda_fp16.h>
#include <cstdint>

#define LATENT   128
#define HIDDEN   2048
#define NPARTS   128
#define KCOLS    2048
#define OMEGA_D  1152
#define TRANZ_D  384
#define TRANSF_D 1536

// ---------------------------------------------------------------------------
// Scratch (__device__ globals; allocation-guard-safe)
// Weight scratch order: w0, w4, w1, w2, w3, w5, w6, w7 (w0/w4 adjacent so the
// merged first layer sees one contiguous [4096, 128] block).
// ---------------------------------------------------------------------------
#define W_TOTAL (2048*128 + 2048*128 + 2048*2048 + 2048*2048 + 1152*2048 + \
                 2048*2048 + 2048*2048 + 384*2048)

__device__ __half g_w_hi[W_TOTAL];
__device__ __half g_act[3][HIDDEN * KCOLS];     // fp16 activations
__device__ __half g_xt[KCOLS * LATENT];
__device__ float g_omega_part[2 * (size_t)KCOLS * OMEGA_D];  // [M][K] layout
__device__ float g_trans_part[3 * (size_t)KCOLS * TRANZ_D];  // [M][K] layout

// ---------------------------------------------------------------------------
// PTX helpers (base ISA: ldmatrix / mma.sync / cp.async)
// ---------------------------------------------------------------------------
__device__ __forceinline__ uint32_t smem_u32(const void* p) {
    uint32_t a;
    asm("{ .reg .u64 t; cvta.to.shared.u64 t, %1; cvt.u32.u64 %0, t; }" : "=r"(a) : "l"(p));
    return a;
}
__device__ __forceinline__ void cp16(uint32_t s, const void* g) {
    asm volatile("cp.async.cg.shared.global [%0], [%1], 16;" :: "r"(s), "l"(g) : "memory");
}
#define CP_COMMIT() asm volatile("cp.async.commit_group;" ::: "memory")

__device__ __forceinline__ void ldsm_x4(uint32_t addr, uint32_t* r) {
    asm volatile("ldmatrix.sync.aligned.m8n8.x4.shared.b16 {%0,%1,%2,%3}, [%4];"
                 : "=r"(r[0]), "=r"(r[1]), "=r"(r[2]), "=r"(r[3]) : "r"(addr));
}
__device__ __forceinline__ void mma_f16(float* c, const uint32_t* a,
                                        uint32_t b0, uint32_t b1) {
    asm volatile(
        "mma.sync.aligned.m16n8k16.row.col.f32.f16.f16.f32 "
        "{%0,%1,%2,%3}, {%4,%5,%6,%7}, {%8,%9}, {%0,%1,%2,%3};"
        : "+f"(c[0]), "+f"(c[1]), "+f"(c[2]), "+f"(c[3])
        : "r"(a[0]), "r"(a[1]), "r"(a[2]), "r"(a[3]), "r"(b0), "r"(b1));
}

// ---------------------------------------------------------------------------
// Fused convert: blocks [0,1024) transpose x -> xt fp16; the rest convert all
// 8 weights -> fp16 into REORDERED scratch (w0,w4,w1,w2,w3,w5,w6,w7), 4-way MLP.
// ---------------------------------------------------------------------------
#define W_CHUNKS 5111808            // total float4 chunks
#define W_STRIDE 1277952            // ceil(W_CHUNKS / 4)
#define XT_BLOCKS 1024              // (2048*128)/256

__global__ __launch_bounds__(256) void convert_all_kernel(
    const float* __restrict__ x,
    const float* __restrict__ w0, const float* __restrict__ w1,
    const float* __restrict__ w2, const float* __restrict__ w3,
    const float* __restrict__ w4, const float* __restrict__ w5,
    const float* __restrict__ w6, const float* __restrict__ w7,
    __half* __restrict__ hi, __half* __restrict__ xt)
{
    if (blockIdx.x < XT_BLOCKS) {
        int i = blockIdx.x * 256 + threadIdx.x;  // i = n*LATENT + f
        int f = i & (LATENT - 1);
        int n = i >> 7;
        xt[i] = __float2half(x[(size_t)f * KCOLS + n]);
        return;
    }
    const int cum[8] = {65536, 1114112, 2162688, 2752512,
                        2818048, 3866624, 4915200, 5111808};
    const int dst[8] = {0, 131072, 1179648, 2228224,
                        65536, 2818048, 3866624, 4915200};
    const float* srcs[8] = {w0, w1, w2, w3, w4, w5, w6, w7};
    const int base = (blockIdx.x - XT_BLOCKS) * 256 + threadIdx.x;

    int   didx[4];
    const float4* gp[4];
    bool  ok[4];
#pragma unroll
    for (int r = 0; r < 4; r++) {
        int idx = base + r * W_STRIDE;
        ok[r] = (idx < W_CHUNKS);
        if (ok[r]) {
            int s = 0;
#pragma unroll
            for (int i = 0; i < 7; i++) s += (idx >= cum[i]);
            int local = idx - (s ? cum[s - 1] : 0);
            gp[r] = (const float4*)srcs[s] + local;
            didx[r] = dst[s] + local;
        } else {
            gp[r] = (const float4*)w0;
            didx[r] = 0;
        }
    }
    float4 v[4];
#pragma unroll
    for (int r = 0; r < 4; r++)
        if (ok[r]) v[r] = *gp[r];
#pragma unroll
    for (int r = 0; r < 4; r++) {
        if (!ok[r]) continue;
        float f[4] = {v[r].x, v[r].y, v[r].z, v[r].w};
        __align__(8) __half h[4];
#pragma unroll
        for (int j = 0; j < 4; j++) h[j] = __float2half(f[j]);
        ((uint2*)hi)[didx[r]] = *(const uint2*)h;
    }
}

// ---------------------------------------------------------------------------
// HMMA GEMM (hi-only):  C = A @ B^T,  A fp16 weights, B fp16 activations.
// mode 0: relu + fp16, output TRANSPOSED [n][M]; if out_h2 != null, rows
//         m0 >= M route to out_h2 at (m0 - M)  (merged dual-output layer).
// mode 1: fp32 raw, output ROW-MAJOR [M][KCOLS].
// CTA 128x128x32, 128 threads (4 warps), warp tile 64x64, 3-stage cp.async,
// 2 CTAs/SM, register-double-buffered ldsm fragments.
// ---------------------------------------------------------------------------
#define BM 128
#define BN 128
#define BK 32
#define GT 128
#define PITCH 80
#define TILE_B (128 * PITCH)      // 10240
#define OFF_AH 0
#define OFF_B  TILE_B
#define STAGE_B (2 * TILE_B)      // 20480
#define NSTAGE 3
#define GEMM_SMEM (128 * 132 * 4) // 67584 (epilogue tile dominates 3*STAGE_B)

__device__ __forceinline__ void load_stage(
    const __half* __restrict__ Ah, const __half* __restrict__ B,
    int Kd, int m0, int n0, int kk, uint32_t stage_sb, int tid)
{
#pragma unroll
    for (int i = 0; i < 8; i++) {
        const int c = tid + i * GT;
        const int row = c >> 2;
        const int cb = (c & 3) * 16;
        const __half* gsrc;
        int grow;
        uint32_t soff;
        if (row < 128) { gsrc = Ah; grow = m0 + row;       soff = OFF_AH + row * PITCH; }
        else           { gsrc = B;  grow = n0 + row - 128; soff = OFF_B  + (row - 128) * PITCH; }
        cp16(stage_sb + soff + cb,
             (const char*)(gsrc + (size_t)grow * Kd + kk) + cb);
    }
}

__global__ __launch_bounds__(GT, 2) void gemm_hmma_kernel(
    const __half* __restrict__ A_hi, const __half* __restrict__ B,
    __half* __restrict__ out_h, __half* __restrict__ out_h2,
    float* __restrict__ out_f32,
    int M, int Kd, int mode, int ktps, size_t out_stride)
{
    extern __shared__ __align__(128) char smem[];
    const uint32_t sb = smem_u32(smem);
    const int tid = threadIdx.x;
    const int lane = tid & 31;
    const int wid = tid >> 5;                 // 0..3
    const int warp_m0 = (wid & 1) * 64;
    const int warp_n0 = (wid >> 1) * 64;
    const int m0 = blockIdx.y * BM;
    const int n0 = blockIdx.x * BN;
    const int KT = Kd / BK;
    const int ktb = blockIdx.z * ktps;
    const int L = min(KT - ktb, ktps);
    out_f32 += (size_t)blockIdx.z * out_stride;

    const int a_row = (lane & 7) + ((lane >> 3) & 1) * 8;
    const int a_kb  = (lane >> 4) * 16;
    const int b_row = (lane & 7) + (lane >> 4) * 8;
    const int b_kb  = ((lane >> 3) & 1) * 16;

    // precomputed intra-stage ldsm offsets
    const uint32_t a_off = (warp_m0 + a_row) * PITCH + a_kb;      // + mt*16*PITCH + kb
    const uint32_t b_off = OFF_B + (warp_n0 + b_row) * PITCH + b_kb; // + g*16*PITCH + kb

    float acc[4][8][4];
#pragma unroll
    for (int mt = 0; mt < 4; mt++)
#pragma unroll
        for (int nt = 0; nt < 8; nt++)
#pragma unroll
            for (int i = 0; i < 4; i++) acc[mt][nt][i] = 0.0f;

    load_stage(A_hi, B, Kd, m0, n0, ktb * BK, sb, tid);
    CP_COMMIT();
    load_stage(A_hi, B, Kd, m0, n0, (ktb + 1) * BK, sb + STAGE_B, tid);
    CP_COMMIT();

    for (int kt = 0; kt < L; kt++) {
        asm volatile("cp.async.wait_group 1;" ::: "memory");
        __syncthreads();

        if (kt + 2 < L) {
            load_stage(A_hi, B, Kd, m0, n0, (ktb + kt + 2) * BK,
                       sb + ((kt + 2) % NSTAGE) * STAGE_B, tid);
        }
        CP_COMMIT();

        const uint32_t st = sb + (kt % NSTAGE) * STAGE_B;

        // register-double-buffered fragments: bqd[ks], ahd[parity]
        uint32_t bqd[2][4][4];
        uint32_t ahd[2][4];

        // prologue: ks=0 B frags + (ks=0, mt=0) A frag
#pragma unroll
        for (int g = 0; g < 4; g++)
            ldsm_x4(st + b_off + g * (16 * PITCH), bqd[0][g]);
        ldsm_x4(st + a_off, ahd[0]);

#pragma unroll
        for (int ks = 0; ks < 2; ks++) {
#pragma unroll
            for (int mt = 0; mt < 4; mt++) {
                const int cur = (ks * 4 + mt) & 1;
                const int nxt = cur ^ 1;
                // prefetch next fragment(s) before consuming current
                if (mt < 3) {
                    ldsm_x4(st + a_off + (mt + 1) * (16 * PITCH) + ks * 32,
                            ahd[nxt]);
                } else if (ks == 0) {
#pragma unroll
                    for (int g = 0; g < 4; g++)
                        ldsm_x4(st + b_off + g * (16 * PITCH) + 32, bqd[1][g]);
                    ldsm_x4(st + a_off + 32, ahd[nxt]);
                }
#pragma unroll
                for (int nt = 0; nt < 8; nt++) {
                    const int g = nt >> 1, p = (nt & 1) * 2;
                    mma_f16(acc[mt][nt], ahd[cur], bqd[ks][g][p], bqd[ks][g][p + 1]);
                }
            }
        }
    }

    // ---------------- epilogue: transpose via SMEM (sC layout [n][m]) ------
    __syncthreads();
    float* sC = (float*)smem;
    const int crow = lane >> 2, ccol = (lane & 3) * 2;
#pragma unroll
    for (int mt = 0; mt < 4; mt++)
#pragma unroll
        for (int nt = 0; nt < 8; nt++) {
            const int m_ = warp_m0 + mt * 16 + crow;
            const int n_ = warp_n0 + nt * 8 + ccol;
            const float* c = acc[mt][nt];
            sC[(size_t)n_ * 132 + m_]           = c[0];
            sC[(size_t)(n_ + 1) * 132 + m_]     = c[1];
            sC[(size_t)n_ * 132 + m_ + 8]       = c[2];
            sC[(size_t)(n_ + 1) * 132 + m_ + 8] = c[3];
        }
    __syncthreads();

    if (mode == 0) {
        // transposed fp16 output [n][M]; dual-output routing for merged layer
        const int r = tid;                // n row 0..127
        __half* dst = out_h;
        int mo = m0;
        if (out_h2 != nullptr && m0 >= M) { dst = out_h2; mo = m0 - M; }
        const size_t base = (size_t)(n0 + r) * M + mo;
        const float* srow = &sC[(size_t)r * 132];
#pragma unroll
        for (int j0 = 0; j0 < 128; j0 += 8) {
            __align__(16) __half h8[8];
#pragma unroll
            for (int j = 0; j < 8; j++)
                h8[j] = __float2half(fmaxf(srow[j0 + j], 0.0f));
            *(uint4*)(dst + base + j0) = *(const uint4*)h8;
        }
    } else {
        // row-major fp32 output [M][KCOLS]: threads span n (coalesced stores)
        const int n_local = tid;
        const float* scol = &sC[(size_t)n_local * 132];
        float* gout = out_f32 + (size_t)m0 * KCOLS + n0 + n_local;
#pragma unroll 8
        for (int mm = 0; mm < 128; mm++)
            gout[(size_t)mm * KCOLS] = scol[mm];
    }
}

// ---------------------------------------------------------------------------
// expm (3x3) + output assembly; partials are [M][K] -> coalesced reads.
// ---------------------------------------------------------------------------
__device__ __forceinline__ void mm3(const float* X, const float* Y, float* Z) {
#pragma unroll
    for (int r = 0; r < 3; r++)
#pragma unroll
        for (int c = 0; c < 3; c++)
            Z[3 * r + c] = fmaf(X[3 * r + 0], Y[c],
                           fmaf(X[3 * r + 1], Y[3 + c], X[3 * r + 2] * Y[6 + c]));
}

__device__ void expm3(const float* A, float* E) {
    float n0 = fabsf(A[0]) + fabsf(A[1]) + fabsf(A[2]);
    float n1 = fabsf(A[3]) + fabsf(A[4]) + fabsf(A[5]);
    float n2 = fabsf(A[6]) + fabsf(A[7]) + fabsf(A[8]);
    float nrm = fmaxf(n0, fmaxf(n1, n2));
    int s = 0;
    if (nrm > 0.25f) {
        s = (int)ceilf(log2f(nrm * 4.0f));
        if (s < 0) s = 0;
    }
    float sc = exp2f((float)(-s));
    float B[9], T[9];
#pragma unroll
    for (int i = 0; i < 9; i++) B[i] = A[i] * sc;
#pragma unroll
    for (int i = 0; i < 9; i++) {
        T[i] = B[i];
        E[i] = ((i == 0) | (i == 4) | (i == 8)) ? 1.0f + B[i] : B[i];
    }
    // 8-term Taylor: truncation ~0.25^8/8! ~ 4e-10 << kernel rel_err budget
#pragma unroll
    for (int j = 2; j <= 8; j++) {
        float Tn[9];
        mm3(T, B, Tn);
        float inv = 1.0f / (float)j;
#pragma unroll
        for (int i = 0; i < 9; i++) { Tn[i] *= inv; E[i] += Tn[i]; T[i] = Tn[i]; }
    }
    for (int q = 0; q < s; q++) {
        float S[9];
        mm3(E, E, S);
#pragma unroll
        for (int i = 0; i < 9; i++) E[i] = S[i];
    }
}

__global__ __launch_bounds__(256) void expm_assemble_kernel(
    const float* __restrict__ omega_part, // 2 x [9n][K]
    const float* __restrict__ trans_part, // 3 x [3n][K]
    float* __restrict__ omega_out,        // (9n, K)
    float* __restrict__ transf,           // (12n, K)
    float* __restrict__ rot,              // (9n, K)
    float* __restrict__ trans_out)        // (3n, K)
{
    const int n = blockIdx.x * 256 + threadIdx.x;
    const int p = blockIdx.y;
    const size_t SO = (size_t)KCOLS * OMEGA_D;
    const size_t ST = (size_t)KCOLS * TRANZ_D;

    float Am[9];
#pragma unroll
    for (int j = 0; j < 9; j++) {
        const size_t off = (size_t)(9 * p + j) * KCOLS + n;
        Am[j] = __ldg(omega_part + off) + __ldg(omega_part + SO + off);
    }

    float E[9];
    expm3(Am, E);

#pragma unroll
    for (int j = 0; j < 9; j++) {
        omega_out[(size_t)(9 * p + j) * KCOLS + n] = Am[j];
        rot[(size_t)(9 * p + j) * KCOLS + n]       = E[j];
        transf[(size_t)(12 * p + j) * KCOLS + n]   = E[j];
    }
#pragma unroll
    for (int c = 0; c < 3; c++) {
        const size_t off = (size_t)(3 * p + c) * KCOLS + n;
        float tv = __ldg(trans_part + off)
                 + __ldg(trans_part + ST + off)
                 + __ldg(trans_part + 2 * ST + off);
        trans_out[(size_t)(3 * p + c) * KCOLS + n]   = tv;
        transf[(size_t)(12 * p + 9 + c) * KCOLS + n] = tv;
    }
}

// ---------------------------------------------------------------------------
// kernel_launch
// ---------------------------------------------------------------------------
extern "C" void kernel_launch(void* const* d_in, const int* in_sizes, int n_in,
                              void* d_out, int out_size)
{
    const float* x = (const float*)d_in[0];
    const float* W[8];
    for (int i = 0; i < 8; i++) W[i] = (const float*)d_in[1 + i];

    // scratch weight element offsets (order: [w0;w4] merged, w1,w2,w3,w5,w6,w7)
    const size_t O_W04 = 0;
    const size_t O_W1  = 524288;
    const size_t O_W2  = 4718592;
    const size_t O_W3  = 8912896;
    const size_t O_W5  = 11272192;
    const size_t O_W6  = 15466496;
    const size_t O_W7  = 19660800;

    float* out    = (float*)d_out;
    float* omega  = out;
    float* transf = omega  + (size_t)OMEGA_D  * KCOLS;
    float* rot    = transf + (size_t)TRANSF_D * KCOLS;
    float* trans  = rot    + (size_t)OMEGA_D  * KCOLS;

    __half *w_hi, *xt, *a0, *a1, *a2;
    float *omega_part, *trans_part;
    cudaGetSymbolAddress((void**)&w_hi, g_w_hi);
    cudaGetSymbolAddress((void**)&xt, g_xt);
    {
        __half* p;
        cudaGetSymbolAddress((void**)&p, g_act);
        a0 = p;
        a1 = p + (size_t)HIDDEN * KCOLS;
        a2 = p + 2 * (size_t)HIDDEN * KCOLS;
    }
    cudaGetSymbolAddress((void**)&omega_part, g_omega_part);
    cudaGetSymbolAddress((void**)&trans_part, g_trans_part);

    cudaFuncSetAttribute(gemm_hmma_kernel,
                         cudaFuncAttributeMaxDynamicSharedMemorySize, GEMM_SMEM);

    // 1) fused convert: xt + all weights (one launch)
    const int wblocks = (W_STRIDE + 255) / 256;
    convert_all_kernel<<<XT_BLOCKS + wblocks, 256>>>(
        x, W[0], W[1], W[2], W[3], W[4], W[5], W[6], W[7], w_hi, xt);

    // 2) GEMM chains (all hi-only)
    auto gemm = [&](size_t wo, const __half* b, __half* oh, float* of,
                    int M, int Kd, int mode, int zsplits, size_t ostride) {
        int KT = Kd / BK;
        int ktps = (KT + zsplits - 1) / zsplits;
        dim3 grid(KCOLS / BN, M / BM, zsplits);
        gemm_hmma_kernel<<<grid, GT, GEMM_SMEM>>>(
            w_hi + wo, b, oh, nullptr, of, M, Kd, mode, ktps, ostride);
    };

    // merged first layer: [w0;w4] (4096 rows) @ xt -> a0 (omega in), a2 (trans in)
    {
        dim3 grid(KCOLS / BN, 4096 / BM, 1);
        gemm_hmma_kernel<<<grid, GT, GEMM_SMEM>>>(
            w_hi + O_W04, xt, a0, a2, nullptr,
            HIDDEN, LATENT, 0, LATENT / BK, 0);
    }

    // omega branch (layer3 split-K x2)
    gemm(O_W1, a0, a1, nullptr, HIDDEN, HIDDEN, 0, 1, 0);
    gemm(O_W2, a1, a0, nullptr, HIDDEN, HIDDEN, 0, 1, 0);
    gemm(O_W3, a0, nullptr, omega_part, OMEGA_D, HIDDEN, 1, 2,
         (size_t)KCOLS * OMEGA_D);
    // translation branch (layer7 split-K x3)
    gemm(O_W5, a2, a1, nullptr, HIDDEN, HIDDEN, 0, 1, 0);
    gemm(O_W6, a1, a2, nullptr, HIDDEN, HIDDEN, 0, 1, 0);
    gemm(O_W7, a2, nullptr, trans_part, TRANZ_D, HIDDEN, 1, 3,
         (size_t)KCOLS * TRANZ_D);

    // 3) expm + assembly
    dim3 ge(KCOLS / 256, NPARTS);
    expm_assemble_kernel<<<ge, 256>>>(omega_part, trans_part, omega, transf,
                                      rot, trans);
}

// round 17
// speedup vs baseline: 1.0457x; 1.0457x over previous
#include <cuda_runtime.h>
#include <cuda_fp16.h>
#include <cstdint>

#define LATENT   128
#define HIDDEN   2048
#define NPARTS   128
#define KCOLS    2048
#define OMEGA_D  1152
#define TRANZ_D  384
#define TRANSF_D 1536

// ---------------------------------------------------------------------------
// Scratch (__device__ globals; allocation-guard-safe)
// Weight scratch order: w0, w4, w1, w2, w3, w5, w6, w7.
// ---------------------------------------------------------------------------
#define W_TOTAL (2048*128 + 2048*128 + 2048*2048 + 2048*2048 + 1152*2048 + \
                 2048*2048 + 2048*2048 + 384*2048)

__device__ __half g_w_hi[W_TOTAL];
__device__ __half g_act[4][HIDDEN * KCOLS];     // fp16 activations (2 chains)
__device__ __half g_xt[KCOLS * LATENT];
__device__ float g_omega_part[2 * (size_t)KCOLS * OMEGA_D];  // [M][K] layout
__device__ float g_trans_part[3 * (size_t)KCOLS * TRANZ_D];  // [M][K] layout

// ---------------------------------------------------------------------------
// PTX helpers
// ---------------------------------------------------------------------------
__device__ __forceinline__ uint32_t smem_u32(const void* p) {
    uint32_t a;
    asm("{ .reg .u64 t; cvta.to.shared.u64 t, %1; cvt.u32.u64 %0, t; }" : "=r"(a) : "l"(p));
    return a;
}
__device__ __forceinline__ void cp16(uint32_t s, const void* g) {
    asm volatile("cp.async.cg.shared.global [%0], [%1], 16;" :: "r"(s), "l"(g) : "memory");
}
#define CP_COMMIT() asm volatile("cp.async.commit_group;" ::: "memory")

__device__ __forceinline__ void ldsm_x4(uint32_t addr, uint32_t* r) {
    asm volatile("ldmatrix.sync.aligned.m8n8.x4.shared.b16 {%0,%1,%2,%3}, [%4];"
                 : "=r"(r[0]), "=r"(r[1]), "=r"(r[2]), "=r"(r[3]) : "r"(addr));
}
__device__ __forceinline__ void mma_f16(float* c, const uint32_t* a,
                                        uint32_t b0, uint32_t b1) {
    asm volatile(
        "mma.sync.aligned.m16n8k16.row.col.f32.f16.f16.f32 "
        "{%0,%1,%2,%3}, {%4,%5,%6,%7}, {%8,%9}, {%0,%1,%2,%3};"
        : "+f"(c[0]), "+f"(c[1]), "+f"(c[2]), "+f"(c[3])
        : "r"(a[0]), "r"(a[1]), "r"(a[2]), "r"(a[3]), "r"(b0), "r"(b1));
}

// ---------------------------------------------------------------------------
// Fused convert: blocks [0,1024) transpose x -> xt fp16; the rest convert all
// 8 weights -> fp16 into REORDERED scratch, 4-way MLP.
// ---------------------------------------------------------------------------
#define W_CHUNKS 5111808
#define W_STRIDE 1277952
#define XT_BLOCKS 1024

__global__ __launch_bounds__(256) void convert_all_kernel(
    const float* __restrict__ x,
    const float* __restrict__ w0, const float* __restrict__ w1,
    const float* __restrict__ w2, const float* __restrict__ w3,
    const float* __restrict__ w4, const float* __restrict__ w5,
    const float* __restrict__ w6, const float* __restrict__ w7,
    __half* __restrict__ hi, __half* __restrict__ xt)
{
    if (blockIdx.x < XT_BLOCKS) {
        int i = blockIdx.x * 256 + threadIdx.x;
        int f = i & (LATENT - 1);
        int n = i >> 7;
        xt[i] = __float2half(x[(size_t)f * KCOLS + n]);
        return;
    }
    const int cum[8] = {65536, 1114112, 2162688, 2752512,
                        2818048, 3866624, 4915200, 5111808};
    const int dst[8] = {0, 131072, 1179648, 2228224,
                        65536, 2818048, 3866624, 4915200};
    const float* srcs[8] = {w0, w1, w2, w3, w4, w5, w6, w7};
    const int base = (blockIdx.x - XT_BLOCKS) * 256 + threadIdx.x;

    int   didx[4];
    const float4* gp[4];
    bool  ok[4];
#pragma unroll
    for (int r = 0; r < 4; r++) {
        int idx = base + r * W_STRIDE;
        ok[r] = (idx < W_CHUNKS);
        if (ok[r]) {
            int s = 0;
#pragma unroll
            for (int i = 0; i < 7; i++) s += (idx >= cum[i]);
            int local = idx - (s ? cum[s - 1] : 0);
            gp[r] = (const float4*)srcs[s] + local;
            didx[r] = dst[s] + local;
        } else {
            gp[r] = (const float4*)w0;
            didx[r] = 0;
        }
    }
    float4 v[4];
#pragma unroll
    for (int r = 0; r < 4; r++)
        if (ok[r]) v[r] = *gp[r];
#pragma unroll
    for (int r = 0; r < 4; r++) {
        if (!ok[r]) continue;
        float f[4] = {v[r].x, v[r].y, v[r].z, v[r].w};
        __align__(8) __half h[4];
#pragma unroll
        for (int j = 0; j < 4; j++) h[j] = __float2half(f[j]);
        ((uint2*)hi)[didx[r]] = *(const uint2*)h;
    }
}

// ---------------------------------------------------------------------------
// Shared GEMM core: CTA 128x128x32, 128 threads, warp tile 64x64,
// 3-stage cp.async, 2 CTAs/SM. Result left in SMEM as sC[n][132] fp32.
// ---------------------------------------------------------------------------
#define BM 128
#define BN 128
#define BK 32
#define GT 128
#define PITCH 80
#define TILE_B (128 * PITCH)
#define OFF_AH 0
#define OFF_B  TILE_B
#define STAGE_B (2 * TILE_B)
#define NSTAGE 3
#define GEMM_SMEM (128 * 132 * 4) // 67584

__device__ __forceinline__ void load_stage(
    const __half* __restrict__ Ah, const __half* __restrict__ B,
    int Kd, int m0, int n0, int kk, uint32_t stage_sb, int tid)
{
#pragma unroll
    for (int i = 0; i < 8; i++) {
        const int c = tid + i * GT;
        const int row = c >> 2;
        const int cb = (c & 3) * 16;
        const __half* gsrc;
        int grow;
        uint32_t soff;
        if (row < 128) { gsrc = Ah; grow = m0 + row;       soff = OFF_AH + row * PITCH; }
        else           { gsrc = B;  grow = n0 + row - 128; soff = OFF_B  + (row - 128) * PITCH; }
        cp16(stage_sb + soff + cb,
             (const char*)(gsrc + (size_t)grow * Kd + kk) + cb);
    }
}

__device__ __forceinline__ void gemm_core(
    const __half* __restrict__ A, const __half* __restrict__ B,
    int Kd, int m0, int n0, int ktb, int L, char* smem)
{
    const uint32_t sb = smem_u32(smem);
    const int tid = threadIdx.x;
    const int lane = tid & 31;
    const int wid = tid >> 5;
    const int warp_m0 = (wid & 1) * 64;
    const int warp_n0 = (wid >> 1) * 64;

    const int a_row = (lane & 7) + ((lane >> 3) & 1) * 8;
    const int a_kb  = (lane >> 4) * 16;
    const int b_row = (lane & 7) + (lane >> 4) * 8;
    const int b_kb  = ((lane >> 3) & 1) * 16;

    float acc[4][8][4];
#pragma unroll
    for (int mt = 0; mt < 4; mt++)
#pragma unroll
        for (int nt = 0; nt < 8; nt++)
#pragma unroll
            for (int i = 0; i < 4; i++) acc[mt][nt][i] = 0.0f;

    load_stage(A, B, Kd, m0, n0, ktb * BK, sb, tid);
    CP_COMMIT();
    load_stage(A, B, Kd, m0, n0, (ktb + 1) * BK, sb + STAGE_B, tid);
    CP_COMMIT();

    for (int kt = 0; kt < L; kt++) {
        asm volatile("cp.async.wait_group 1;" ::: "memory");
        __syncthreads();

        if (kt + 2 < L) {
            load_stage(A, B, Kd, m0, n0, (ktb + kt + 2) * BK,
                       sb + ((kt + 2) % NSTAGE) * STAGE_B, tid);
        }
        CP_COMMIT();

        const uint32_t st = sb + (kt % NSTAGE) * STAGE_B;
#pragma unroll
        for (int ks = 0; ks < 2; ks++) {
            const int kb = ks * 32;
            uint32_t bq[4][4];
#pragma unroll
            for (int g = 0; g < 4; g++) {
                uint32_t rb = st + OFF_B + (warp_n0 + g * 16 + b_row) * PITCH + kb + b_kb;
                ldsm_x4(rb, bq[g]);
            }
#pragma unroll
            for (int mt = 0; mt < 4; mt++) {
                uint32_t ah[4];
                uint32_t ra = st + (warp_m0 + mt * 16 + a_row) * PITCH + kb + a_kb;
                ldsm_x4(ra + OFF_AH, ah);
#pragma unroll
                for (int nt = 0; nt < 8; nt++) {
                    const int g = nt >> 1, p = (nt & 1) * 2;
                    mma_f16(acc[mt][nt], ah, bq[g][p], bq[g][p + 1]);
                }
            }
        }
    }

    // transpose accumulators into SMEM tile sC[n][132]
    __syncthreads();
    float* sC = (float*)smem;
    const int crow = lane >> 2, ccol = (lane & 3) * 2;
#pragma unroll
    for (int mt = 0; mt < 4; mt++)
#pragma unroll
        for (int nt = 0; nt < 8; nt++) {
            const int m_ = warp_m0 + mt * 16 + crow;
            const int n_ = warp_n0 + nt * 8 + ccol;
            const float* c = acc[mt][nt];
            sC[(size_t)n_ * 132 + m_]           = c[0];
            sC[(size_t)(n_ + 1) * 132 + m_]     = c[1];
            sC[(size_t)n_ * 132 + m_ + 8]       = c[2];
            sC[(size_t)(n_ + 1) * 132 + m_ + 8] = c[3];
        }
    __syncthreads();
}

// ---------------------------------------------------------------------------
// Batched pair GEMM (mode 0): grid.y in [0,32). y<16 -> half 0, else half 1.
// out = relu(A @ B^T) as fp16, TRANSPOSED [n][2048].
// ---------------------------------------------------------------------------
__global__ __launch_bounds__(GT, 2) void gemm_pair_kernel(
    const __half* __restrict__ A0, const __half* __restrict__ B0,
    __half* __restrict__ O0,
    const __half* __restrict__ A1, const __half* __restrict__ B1,
    __half* __restrict__ O1, int Kd)
{
    extern __shared__ __align__(128) char smem[];
    const int yy = blockIdx.y;
    const __half* A;
    const __half* B;
    __half* O;
    int m0;
    if (yy < 16) { A = A0; B = B0; O = O0; m0 = yy * BM; }
    else         { A = A1; B = B1; O = O1; m0 = (yy - 16) * BM; }
    const int n0 = blockIdx.x * BN;
    const int KT = Kd / BK;

    gemm_core(A, B, Kd, m0, n0, 0, KT, smem);

    const float* sC = (const float*)smem;
    const int r = threadIdx.x;            // n row 0..127
    const size_t base = (size_t)(n0 + r) * HIDDEN + m0;
    const float* srow = &sC[(size_t)r * 132];
#pragma unroll
    for (int j0 = 0; j0 < 128; j0 += 8) {
        __align__(16) __half h8[8];
#pragma unroll
        for (int j = 0; j < 8; j++)
            h8[j] = __float2half(fmaxf(srow[j0 + j], 0.0f));
        *(uint4*)(O + base + j0) = *(const uint4*)h8;
    }
}

// ---------------------------------------------------------------------------
// Batched final GEMM (mode 1): grid.y in [0,27).
//  y in [0,18):  L3  (omega head, M=1152, split-K x2): m-tile=y/2, z=y%2, ktps=32
//  y in [18,27): L7  (trans head, M=384,  split-K x3): m-tile=u/3, z=u%3, ktps=22
// fp32 output ROW-MAJOR [M][KCOLS] + z*ostride.
// ---------------------------------------------------------------------------
__global__ __launch_bounds__(GT, 2) void gemm_final_kernel(
    const __half* __restrict__ A3, const __half* __restrict__ B3,
    float* __restrict__ O3,
    const __half* __restrict__ A7, const __half* __restrict__ B7,
    float* __restrict__ O7)
{
    extern __shared__ __align__(128) char smem[];
    const int y = blockIdx.y;
    const __half* A;
    const __half* B;
    float* O;
    int m0, z, ktps;
    size_t ostride;
    if (y < 18) {
        A = A3; B = B3; O = O3;
        m0 = (y >> 1) * BM; z = y & 1; ktps = 32;
        ostride = (size_t)KCOLS * OMEGA_D;
    } else {
        const int u = y - 18;
        A = A7; B = B7; O = O7;
        m0 = (u / 3) * BM; z = u % 3; ktps = 22;
        ostride = (size_t)KCOLS * TRANZ_D;
    }
    O += (size_t)z * ostride;
    const int n0 = blockIdx.x * BN;
    const int KT = KCOLS / BK;           // Kd = 2048
    const int ktb = z * ktps;
    const int L = min(KT - ktb, ktps);

    gemm_core(A, B, KCOLS, m0, n0, ktb, L, smem);

    const float* sC = (const float*)smem;
    const int n_local = threadIdx.x;
    const float* scol = &sC[(size_t)n_local * 132];
    float* gout = O + (size_t)m0 * KCOLS + n0 + n_local;
#pragma unroll 8
    for (int mm = 0; mm < 128; mm++)
        gout[(size_t)mm * KCOLS] = scol[mm];
}

// ---------------------------------------------------------------------------
// expm (3x3) + output assembly; partials are [M][K] -> coalesced reads.
// ---------------------------------------------------------------------------
__device__ __forceinline__ void mm3(const float* X, const float* Y, float* Z) {
#pragma unroll
    for (int r = 0; r < 3; r++)
#pragma unroll
        for (int c = 0; c < 3; c++)
            Z[3 * r + c] = fmaf(X[3 * r + 0], Y[c],
                           fmaf(X[3 * r + 1], Y[3 + c], X[3 * r + 2] * Y[6 + c]));
}

__device__ void expm3(const float* A, float* E) {
    float n0 = fabsf(A[0]) + fabsf(A[1]) + fabsf(A[2]);
    float n1 = fabsf(A[3]) + fabsf(A[4]) + fabsf(A[5]);
    float n2 = fabsf(A[6]) + fabsf(A[7]) + fabsf(A[8]);
    float nrm = fmaxf(n0, fmaxf(n1, n2));
    int s = 0;
    if (nrm > 0.25f) {
        s = (int)ceilf(log2f(nrm * 4.0f));
        if (s < 0) s = 0;
    }
    float sc = exp2f((float)(-s));
    float B[9], T[9];
#pragma unroll
    for (int i = 0; i < 9; i++) B[i] = A[i] * sc;
#pragma unroll
    for (int i = 0; i < 9; i++) {
        T[i] = B[i];
        E[i] = ((i == 0) | (i == 4) | (i == 8)) ? 1.0f + B[i] : B[i];
    }
#pragma unroll
    for (int j = 2; j <= 8; j++) {
        float Tn[9];
        mm3(T, B, Tn);
        float inv = 1.0f / (float)j;
#pragma unroll
        for (int i = 0; i < 9; i++) { Tn[i] *= inv; E[i] += Tn[i]; T[i] = Tn[i]; }
    }
    for (int q = 0; q < s; q++) {
        float S[9];
        mm3(E, E, S);
#pragma unroll
        for (int i = 0; i < 9; i++) E[i] = S[i];
    }
}

__global__ __launch_bounds__(256) void expm_assemble_kernel(
    const float* __restrict__ omega_part, // 2 x [9n][K]
    const float* __restrict__ trans_part, // 3 x [3n][K]
    float* __restrict__ omega_out,        // (9n, K)
    float* __restrict__ transf,           // (12n, K)
    float* __restrict__ rot,              // (9n, K)
    float* __restrict__ trans_out)        // (3n, K)
{
    const int n = blockIdx.x * 256 + threadIdx.x;
    const int p = blockIdx.y;
    const size_t SO = (size_t)KCOLS * OMEGA_D;
    const size_t ST = (size_t)KCOLS * TRANZ_D;

    float Am[9];
#pragma unroll
    for (int j = 0; j < 9; j++) {
        const size_t off = (size_t)(9 * p + j) * KCOLS + n;
        Am[j] = __ldg(omega_part + off) + __ldg(omega_part + SO + off);
    }

    float E[9];
    expm3(Am, E);

#pragma unroll
    for (int j = 0; j < 9; j++) {
        omega_out[(size_t)(9 * p + j) * KCOLS + n] = Am[j];
        rot[(size_t)(9 * p + j) * KCOLS + n]       = E[j];
        transf[(size_t)(12 * p + j) * KCOLS + n]   = E[j];
    }
#pragma unroll
    for (int c = 0; c < 3; c++) {
        const size_t off = (size_t)(3 * p + c) * KCOLS + n;
        float tv = __ldg(trans_part + off)
                 + __ldg(trans_part + ST + off)
                 + __ldg(trans_part + 2 * ST + off);
        trans_out[(size_t)(3 * p + c) * KCOLS + n]   = tv;
        transf[(size_t)(12 * p + 9 + c) * KCOLS + n] = tv;
    }
}

// ---------------------------------------------------------------------------
// kernel_launch
// ---------------------------------------------------------------------------
extern "C" void kernel_launch(void* const* d_in, const int* in_sizes, int n_in,
                              void* d_out, int out_size)
{
    const float* x = (const float*)d_in[0];
    const float* W[8];
    for (int i = 0; i < 8; i++) W[i] = (const float*)d_in[1 + i];

    // scratch weight element offsets (order: w0, w4, w1, w2, w3, w5, w6, w7)
    const size_t O_W0  = 0;
    const size_t O_W4  = 262144;
    const size_t O_W1  = 524288;
    const size_t O_W2  = 4718592;
    const size_t O_W3  = 8912896;
    const size_t O_W5  = 11272192;
    const size_t O_W6  = 15466496;
    const size_t O_W7  = 19660800;

    float* out    = (float*)d_out;
    float* omega  = out;
    float* transf = omega  + (size_t)OMEGA_D  * KCOLS;
    float* rot    = transf + (size_t)TRANSF_D * KCOLS;
    float* trans  = rot    + (size_t)OMEGA_D  * KCOLS;

    __half *w_hi, *xt, *a0, *a1, *a2, *a3;
    float *omega_part, *trans_part;
    cudaGetSymbolAddress((void**)&w_hi, g_w_hi);
    cudaGetSymbolAddress((void**)&xt, g_xt);
    {
        __half* p;
        cudaGetSymbolAddress((void**)&p, g_act);
        a0 = p;
        a1 = p + 1 * (size_t)HIDDEN * KCOLS;
        a2 = p + 2 * (size_t)HIDDEN * KCOLS;
        a3 = p + 3 * (size_t)HIDDEN * KCOLS;
    }
    cudaGetSymbolAddress((void**)&omega_part, g_omega_part);
    cudaGetSymbolAddress((void**)&trans_part, g_trans_part);

    cudaFuncSetAttribute(gemm_pair_kernel,
                         cudaFuncAttributeMaxDynamicSharedMemorySize, GEMM_SMEM);
    cudaFuncSetAttribute(gemm_final_kernel,
                         cudaFuncAttributeMaxDynamicSharedMemorySize, GEMM_SMEM);

    // 1) fused convert: xt + all weights (one launch)
    const int wblocks = (W_STRIDE + 255) / 256;
    convert_all_kernel<<<XT_BLOCKS + wblocks, 256>>>(
        x, W[0], W[1], W[2], W[3], W[4], W[5], W[6], W[7], w_hi, xt);

    dim3 pair_grid(KCOLS / BN, 32);

    // 2) stage 0: L0 (omega) + L4 (trans) from xt   [Kd = 128]
    gemm_pair_kernel<<<pair_grid, GT, GEMM_SMEM>>>(
        w_hi + O_W0, xt, a0,
        w_hi + O_W4, xt, a2, LATENT);

    // 3) stage 1: L1 (a0 -> a1) + L5 (a2 -> a3)     [Kd = 2048]
    gemm_pair_kernel<<<pair_grid, GT, GEMM_SMEM>>>(
        w_hi + O_W1, a0, a1,
        w_hi + O_W5, a2, a3, HIDDEN);

    // 4) stage 2: L2 (a1 -> a0) + L6 (a3 -> a2)
    gemm_pair_kernel<<<pair_grid, GT, GEMM_SMEM>>>(
        w_hi + O_W2, a1, a0,
        w_hi + O_W6, a3, a2, HIDDEN);

    // 5) stage 3: L3 (a0 -> omega_part, sK2) + L7 (a2 -> trans_part, sK3)
    dim3 final_grid(KCOLS / BN, 27);
    gemm_final_kernel<<<final_grid, GT, GEMM_SMEM>>>(
        w_hi + O_W3, a0, omega_part,
        w_hi + O_W7, a2, trans_part);

    // 6) expm + assembly
    dim3 ge(KCOLS / 256, NPARTS);
    expm_assemble_kernel<<<ge, 256>>>(omega_part, trans_part, omega, transf,
                                      rot, trans);
}